// round 1
// baseline (speedup 1.0000x reference)
#include <cuda_runtime.h>
#include <cuda_bf16.h>

// FlowBasedDensityPotential: energy = 0.5 * sum(|grad phi|^2) with central
// differences (one-sided at boundaries) on a 2048x2048 f32 grid.
// 'pos' input is dead (never affects the output) and is ignored.

#define NX 2048
#define NY 2048
#define RPT 4                         // rows per thread (rolling window)
#define BLOCK 256
#define CHUNKS_PER_BAND (NY / 4)      // 512 float4 chunks per row band
#define NUM_BANDS (NX / RPT)          // 512
#define TOTAL_THREADS (CHUNKS_PER_BAND * NUM_BANDS)   // 262144
#define NUM_BLOCKS (TOTAL_THREADS / BLOCK)            // 1024

__device__ double       g_partials[NUM_BLOCKS];
__device__ unsigned int g_ticket = 0;

__global__ void __launch_bounds__(BLOCK)
flow_energy_kernel(const float* __restrict__ phi, float* __restrict__ out)
{
    const int t    = blockIdx.x * BLOCK + threadIdx.x;
    const int jc   = t & (CHUNKS_PER_BAND - 1);   // chunk index along y (contiguous in warp)
    const int band = t >> 9;                      // row band index
    const int j0   = jc * 4;
    const int i0   = band * RPT;

    const float C1 = 1024.0f;   // 1/(2h), h = 1/2048
    const float C2 = 2048.0f;   // 1/h (one-sided boundary)

    float acc = 0.0f;

    float4 prev, cur, next;
    cur = *reinterpret_cast<const float4*>(phi + (size_t)i0 * NY + j0);
    if (i0 > 0)
        prev = *reinterpret_cast<const float4*>(phi + (size_t)(i0 - 1) * NY + j0);
    else
        prev = cur;   // unused at i==0 (forward diff there)
    next = cur;

    #pragma unroll
    for (int r = 0; r < RPT; ++r) {
        const int i = i0 + r;
        const size_t row = (size_t)i * NY;
        if (i < NX - 1)
            next = *reinterpret_cast<const float4*>(phi + row + NY + j0);

        // x-direction gradient (sign irrelevant; squared)
        float4 dx;
        if (i == 0) {
            dx.x = (next.x - cur.x) * C2;
            dx.y = (next.y - cur.y) * C2;
            dx.z = (next.z - cur.z) * C2;
            dx.w = (next.w - cur.w) * C2;
        } else if (i == NX - 1) {
            dx.x = (cur.x - prev.x) * C2;
            dx.y = (cur.y - prev.y) * C2;
            dx.z = (cur.z - prev.z) * C2;
            dx.w = (cur.w - prev.w) * C2;
        } else {
            dx.x = (next.x - prev.x) * C1;
            dx.y = (next.y - prev.y) * C1;
            dx.z = (next.z - prev.z) * C1;
            dx.w = (next.w - prev.w) * C1;
        }

        // y-direction gradient: neighbors within the float4 + 1 scalar halo each side
        float left  = (j0 > 0)      ? phi[row + j0 - 1] : 0.0f;
        float right = (j0 + 4 < NY) ? phi[row + j0 + 4] : 0.0f;

        float dy0 = (j0 == 0)      ? (cur.y - cur.x) * C2 : (cur.y - left)  * C1;
        float dy1 = (cur.z - cur.x) * C1;
        float dy2 = (cur.w - cur.y) * C1;
        float dy3 = (j0 + 4 == NY) ? (cur.w - cur.z) * C2 : (right - cur.z) * C1;

        acc += dx.x * dx.x + dy0 * dy0;
        acc += dx.y * dx.y + dy1 * dy1;
        acc += dx.z * dx.z + dy2 * dy2;
        acc += dx.w * dx.w + dy3 * dy3;

        prev = cur;
        cur  = next;
    }

    // ---- block reduction (float tree; <= 16 terms/thread so f32 is exact enough) ----
    #pragma unroll
    for (int off = 16; off; off >>= 1)
        acc += __shfl_xor_sync(0xffffffffu, acc, off);

    __shared__ float  s_warp[BLOCK / 32];
    __shared__ bool   s_is_last;
    if ((threadIdx.x & 31) == 0)
        s_warp[threadIdx.x >> 5] = acc;
    __syncthreads();

    if (threadIdx.x < 32) {
        float v = (threadIdx.x < BLOCK / 32) ? s_warp[threadIdx.x] : 0.0f;
        #pragma unroll
        for (int off = 4; off; off >>= 1)
            v += __shfl_xor_sync(0xffffffffu, v, off);
        if (threadIdx.x == 0) {
            g_partials[blockIdx.x] = (double)v;
            __threadfence();
            unsigned int tk = atomicAdd(&g_ticket, 1u);
            s_is_last = (tk == (unsigned int)(gridDim.x - 1));
        }
    }
    __syncthreads();

    // ---- last block: sum the 1024 double partials, write scalar, reset ticket ----
    if (s_is_last) {
        double d = 0.0;
        for (int k = threadIdx.x; k < NUM_BLOCKS; k += BLOCK)
            d += g_partials[k];
        #pragma unroll
        for (int off = 16; off; off >>= 1)
            d += __shfl_xor_sync(0xffffffffu, d, off);

        __shared__ double s_dwarp[BLOCK / 32];
        if ((threadIdx.x & 31) == 0)
            s_dwarp[threadIdx.x >> 5] = d;
        __syncthreads();
        if (threadIdx.x < 32) {
            double v = (threadIdx.x < BLOCK / 32) ? s_dwarp[threadIdx.x] : 0.0;
            #pragma unroll
            for (int off = 4; off; off >>= 1)
                v += __shfl_xor_sync(0xffffffffu, v, off);
            if (threadIdx.x == 0) {
                out[0] = (float)(0.5 * v);
                g_ticket = 0;   // reset for next (graph-replayed) launch
            }
        }
    }
}

extern "C" void kernel_launch(void* const* d_in, const int* in_sizes, int n_in,
                              void* d_out, int out_size)
{
    // Select phi by element count (2048*2048); 'pos' (2,000,000 elems) is unused.
    const float* phi = nullptr;
    for (int i = 0; i < n_in; ++i) {
        if (in_sizes[i] == NX * NY) { phi = (const float*)d_in[i]; break; }
    }
    if (!phi) phi = (const float*)d_in[n_in - 1];   // fallback: last input

    flow_energy_kernel<<<NUM_BLOCKS, BLOCK>>>(phi, (float*)d_out);
}